// round 2
// baseline (speedup 1.0000x reference)
#include <cuda_runtime.h>
#include <math.h>

#define NN 100000
#define CC 128
#define EE 600000
#define HH 64
#define TILE 64
#define NTILES (EE / TILE)      // 9375 exactly
#define MAIN_GRID 456           // 152 SMs * 3 blocks
#define MAIN_THREADS 128

// Scratch node tables: v1 = z_out + z_self, v2 = z_in + z_self  (51.2 MB each)
__device__ float g_v1[(size_t)NN * CC];
__device__ float g_v2[(size_t)NN * CC];

__global__ void prep_kernel(const float* __restrict__ z_in,
                            const float* __restrict__ z_out,
                            const float* __restrict__ z_self) {
    int i = blockIdx.x * blockDim.x + threadIdx.x;   // exact grid: NN*CC/4 threads
    const float4* zi = (const float4*)z_in;
    const float4* zo = (const float4*)z_out;
    const float4* zs = (const float4*)z_self;
    float4* v1 = (float4*)g_v1;
    float4* v2 = (float4*)g_v2;
    float4 s = zs[i];
    float4 a = zo[i];
    float4 b = zi[i];
    float4 r1, r2;
    r1.x = a.x + s.x; r1.y = a.y + s.y; r1.z = a.z + s.z; r1.w = a.w + s.w;
    r2.x = b.x + s.x; r2.y = b.y + s.y; r2.z = b.z + s.z; r2.w = b.w + s.w;
    v1[i] = r1;
    v2[i] = r2;
}

// Fused gather + GEMM(E x 64 x 128) + ELU + GEMV + sigmoid.
// Per tile of 64 edges: A^T tile [K=128][M=64] in SMEM (XOR-swizzled on
// float4 groups of the edge index for conflict-light transposed stores),
// W1 [128][64] resident in SMEM. Thread tile 8M x 4N with packed-fp32 FFMA2
// (accumulator pairs over adjacent edges).
__global__ __launch_bounds__(MAIN_THREADS) void gemm_kernel(
    const int* __restrict__ eidx,          // int32 (JAX x64-disabled downgrade)
    const float* __restrict__ W1,
    const float* __restrict__ b1,
    const float* __restrict__ W2,
    const float* __restrict__ b2,
    float* __restrict__ out)
{
    extern __shared__ float smem[];
    float* As  = smem;            // 128*64 = 8192 floats (A^T, swizzled)
    float* Bs  = smem + 8192;     // 128*64 (W1, row-major as given)
    float* b1s = smem + 16384;    // 64
    float* w2s = smem + 16448;    // 64
    float* red = smem + 16512;    // 64*16 partial-logit reduction

    const int tid  = threadIdx.x;
    const int lane = tid & 31;
    const int warp = tid >> 5;
    const int row  = tid >> 4;    // 0..7  -> m base = row*8
    const int col  = tid & 15;    // 0..15 -> n base = col*4

    // Load weights once per (persistent) block
    for (int i = tid; i < CC * HH; i += MAIN_THREADS) Bs[i] = W1[i];
    if (tid < HH) { b1s[tid] = b1[tid]; w2s[tid] = W2[tid]; }
    const float b2v = b2[0];
    __syncthreads();

    const int* srcI = eidx;
    const int* dstI = eidx + EE;

    for (int tile = blockIdx.x; tile < NTILES; tile += MAIN_GRID) {
        const int e0 = tile * TILE;

        // ---- Gather: each warp handles 16 edges; one warp-iteration = one
        // edge row, fully coalesced 512B LDG bursts from each node table. ----
        {
            const int ebase = e0 + warp * 16;
            int myid = 0;
            if (lane < 16) myid = srcI[ebase + lane];
            else           myid = dstI[ebase + lane - 16];
            #pragma unroll 4
            for (int i = 0; i < 16; i++) {
                const int src = __shfl_sync(0xffffffffu, myid, i);
                const int dst = __shfl_sync(0xffffffffu, myid, 16 + i);
                const int el  = warp * 16 + i;   // edge index within tile
                float4 a = *(const float4*)(g_v1 + (size_t)src * CC + lane * 4);
                float4 b = *(const float4*)(g_v2 + (size_t)dst * CC + lane * 4);
                float4 p;
                p.x = a.x * b.x; p.y = a.y * b.y; p.z = a.z * b.z; p.w = a.w * b.w;
                // store transposed As[c][e'] with e' group = (el/4) ^ (c/4 & 7)
                const int cq = (((el >> 2) ^ (lane & 7)) << 2) + (el & 3);
                As[(4 * lane + 0) * 64 + cq] = p.x;
                As[(4 * lane + 1) * 64 + cq] = p.y;
                As[(4 * lane + 2) * 64 + cq] = p.z;
                As[(4 * lane + 3) * 64 + cq] = p.w;
            }
        }
        __syncthreads();

        // ---- Main loop: D[64e x 64h] += A^T x W1, packed fp32 (FFMA2) ----
        unsigned long long acc[4][4];
        #pragma unroll
        for (int mp = 0; mp < 4; mp++)
            #pragma unroll
            for (int j = 0; j < 4; j++) acc[mp][j] = 0ull;   // two packed 0.0f

        #pragma unroll 8
        for (int k = 0; k < CC; k++) {
            const int s  = (k >> 2) & 7;
            const int g0 = (row << 1) ^ s;   // swizzled float4-group of m-base
            const ulonglong2* As2 = (const ulonglong2*)(As + k * 64);
            const ulonglong2 A0 = As2[g0];
            const ulonglong2 A1 = As2[g0 ^ 1];
            const unsigned long long am[4] = {A0.x, A0.y, A1.x, A1.y};
            const float4 b4 = *(const float4*)(Bs + k * 64 + col * 4);
            unsigned long long bb[4];
            asm("mov.b64 %0, {%1, %1};" : "=l"(bb[0]) : "f"(b4.x));
            asm("mov.b64 %0, {%1, %1};" : "=l"(bb[1]) : "f"(b4.y));
            asm("mov.b64 %0, {%1, %1};" : "=l"(bb[2]) : "f"(b4.z));
            asm("mov.b64 %0, {%1, %1};" : "=l"(bb[3]) : "f"(b4.w));
            #pragma unroll
            for (int mp = 0; mp < 4; mp++)
                #pragma unroll
                for (int j = 0; j < 4; j++)
                    asm("fma.rn.f32x2 %0, %1, %2, %0;"
                        : "+l"(acc[mp][j]) : "l"(am[mp]), "l"(bb[j]));
        }

        // ---- Epilogue: bias + ELU + dot(W2) partials ----
        float p[8];
        #pragma unroll
        for (int i = 0; i < 8; i++) p[i] = 0.f;
        #pragma unroll
        for (int mp = 0; mp < 4; mp++) {
            #pragma unroll
            for (int j = 0; j < 4; j++) {
                const int n = col * 4 + j;
                const float f0 = __uint_as_float((unsigned)(acc[mp][j] & 0xffffffffull));
                const float f1 = __uint_as_float((unsigned)(acc[mp][j] >> 32));
                const float x0 = f0 + b1s[n];
                const float x1 = f1 + b1s[n];
                const float h0 = x0 > 0.f ? x0 : expm1f(x0);
                const float h1 = x1 > 0.f ? x1 : expm1f(x1);
                const float w = w2s[n];
                p[2 * mp]     += h0 * w;
                p[2 * mp + 1] += h1 * w;
            }
        }
        #pragma unroll
        for (int i = 0; i < 8; i++) red[(row * 8 + i) * 16 + col] = p[i];
        __syncthreads();

        if (tid < TILE) {
            float sacc = b2v;
            #pragma unroll
            for (int c2 = 0; c2 < 16; c2++) sacc += red[tid * 16 + c2];
            out[e0 + tid] = 1.0f / (1.0f + expf(-sacc));
        }
        __syncthreads();   // protect As/red before next tile
    }
}

extern "C" void kernel_launch(void* const* d_in, const int* in_sizes, int n_in,
                              void* d_out, int out_size) {
    const float* z_in   = (const float*)d_in[0];
    const float* z_out  = (const float*)d_in[1];
    const float* z_self = (const float*)d_in[2];
    const int*   eidx   = (const int*)d_in[3];
    const float* W1     = (const float*)d_in[4];
    const float* b1     = (const float*)d_in[5];
    const float* W2     = (const float*)d_in[6];
    const float* b2     = (const float*)d_in[7];
    float*       outp   = (float*)d_out;

    // 1) node tables: exact grid, NN*CC/4 float4 elements
    prep_kernel<<<NN * CC / 4 / 256, 256>>>(z_in, z_out, z_self);

    // 2) fused gather + GEMM + epilogue
    const int smem_bytes = (8192 + 8192 + 64 + 64 + 64 * 16) * (int)sizeof(float); // 70144
    cudaFuncSetAttribute(gemm_kernel,
                         cudaFuncAttributeMaxDynamicSharedMemorySize, smem_bytes);
    gemm_kernel<<<MAIN_GRID, MAIN_THREADS, smem_bytes>>>(eidx, W1, b1, W2, b2, outp);
}

// round 4
// speedup vs baseline: 1.8241x; 1.8241x over previous
#include <cuda_runtime.h>
#include <math.h>
#include <stdint.h>

#define NN 100000
#define CC 128
#define EE 600000
#define HH 64
#define TILE 64
#define NTILES (EE / TILE)      // 9375 exactly, no tail
#define MAIN_GRID 456           // ~3 blocks/SM persistent
#define MAIN_THREADS 128

#define AP 132                  // As pitch (floats): 128 + 4 pad -> conflict-free frags
#define BP 68                   // Bs pitch (floats): 64 + 4 pad

// SMEM float offsets
#define OFF_B  0                // 128*68  = 8704
#define OFF_A  8704             // 64*132  = 8448
#define OFF_B1 17152            // 64
#define OFF_W2 17216            // 64
#define SMEM_FLOATS 17280       // 69120 bytes

// Scratch node tables: v1 = z_out + z_self, v2 = z_in + z_self
__device__ float g_v1[(size_t)NN * CC];
__device__ float g_v2[(size_t)NN * CC];

__global__ void prep_kernel(const float* __restrict__ z_in,
                            const float* __restrict__ z_out,
                            const float* __restrict__ z_self) {
    int i = blockIdx.x * blockDim.x + threadIdx.x;
    const float4* zi = (const float4*)z_in;
    const float4* zo = (const float4*)z_out;
    const float4* zs = (const float4*)z_self;
    float4* v1 = (float4*)g_v1;
    float4* v2 = (float4*)g_v2;
    float4 s = zs[i];
    float4 a = zo[i];
    float4 b = zi[i];
    float4 r1, r2;
    r1.x = a.x + s.x; r1.y = a.y + s.y; r1.z = a.z + s.z; r1.w = a.w + s.w;
    r2.x = b.x + s.x; r2.y = b.y + s.y; r2.z = b.z + s.z; r2.w = b.w + s.w;
    v1[i] = r1;
    v2[i] = r2;
}

__device__ __forceinline__ uint32_t f2tf32(float f) {
    uint32_t u;
    asm("cvt.rna.tf32.f32 %0, %1;" : "=r"(u) : "f"(f));
    return u;
}

__device__ __forceinline__ void mma_tf32(float* c,
                                         uint32_t a0, uint32_t a1, uint32_t a2, uint32_t a3,
                                         uint32_t b0, uint32_t b1) {
    asm volatile(
        "mma.sync.aligned.m16n8k8.row.col.f32.tf32.tf32.f32 "
        "{%0,%1,%2,%3}, {%4,%5,%6,%7}, {%8,%9}, {%0,%1,%2,%3};"
        : "+f"(c[0]), "+f"(c[1]), "+f"(c[2]), "+f"(c[3])
        : "r"(a0), "r"(a1), "r"(a2), "r"(a3), "r"(b0), "r"(b1));
}

// Fused gather + GEMM(64x64x128 per tile, mma.sync tf32) + ELU + GEMV + sigmoid.
// Each warp owns 16 edges of the tile and its own 16 rows of As: the tile
// loop is barrier-free (warps fully independent after weight staging).
__global__ __launch_bounds__(MAIN_THREADS, 1)
void gemm_kernel(const int* __restrict__ eidx,
                 const float* __restrict__ W1,
                 const float* __restrict__ b1,
                 const float* __restrict__ W2,
                 const float* __restrict__ b2,
                 float* __restrict__ out)
{
    extern __shared__ float smem[];
    uint32_t* Bu  = (uint32_t*)(smem + OFF_B);
    uint32_t* Au  = (uint32_t*)(smem + OFF_A);
    float*    b1s = smem + OFF_B1;
    float*    w2s = smem + OFF_W2;

    const int tid  = threadIdx.x;
    const int lane = tid & 31;
    const int warp = tid >> 5;
    const int gid  = lane >> 2;   // 0..7
    const int tig  = lane & 3;    // 0..3
    const int wb   = warp * 16;   // A-row base for this warp

    // ---- Stage W1^ (as [k][n], tf32) + vectors, once per persistent block ----
    for (int i = tid; i < CC * HH; i += MAIN_THREADS) {
        const int k = i >> 6, n = i & 63;
        Bu[k * BP + n] = f2tf32(W1[i]);
    }
    if (tid < HH) { b1s[tid] = b1[tid]; w2s[tid] = W2[tid]; }
    const float b2v = b2[0];
    __syncthreads();

    const int* srcI = eidx;
    const int* dstI = eidx + EE;

    for (int tile = blockIdx.x; tile < NTILES; tile += MAIN_GRID) {
        const int e0 = tile * TILE;

        // ---- Gather + product + tf32 store into As[m][k] (row-major, pitch AP) ----
        {
            const int ebase = e0 + wb;
            const int my = (lane < 16) ? srcI[ebase + lane] : dstI[ebase + lane - 16];
            #pragma unroll 4
            for (int i = 0; i < 16; i++) {
                const int src = __shfl_sync(0xffffffffu, my, i);
                const int dst = __shfl_sync(0xffffffffu, my, 16 + i);
                float4 a = *(const float4*)(g_v1 + (size_t)src * CC + lane * 4);
                float4 b = *(const float4*)(g_v2 + (size_t)dst * CC + lane * 4);
                uint4 p;
                p.x = f2tf32(a.x * b.x);
                p.y = f2tf32(a.y * b.y);
                p.z = f2tf32(a.z * b.z);
                p.w = f2tf32(a.w * b.w);
                *(uint4*)(Au + (wb + i) * AP + lane * 4) = p;   // STS.128, conflict-free
            }
        }
        __syncwarp();   // warp-local producer->consumer on As rows

        // ---- GEMM: D[16x64] per warp = A[16x128] x B[128x64] ----
        float acc[8][4];
        #pragma unroll
        for (int nt = 0; nt < 8; nt++)
            #pragma unroll
            for (int j = 0; j < 4; j++) acc[nt][j] = 0.f;

        #pragma unroll 4
        for (int ks = 0; ks < 16; ks++) {
            const int k0 = ks * 8;
            const uint32_t* ar = Au + (wb + gid) * AP + k0 + tig;
            const uint32_t a0 = ar[0];
            const uint32_t a2 = ar[4];
            const uint32_t a1 = ar[8 * AP];
            const uint32_t a3 = ar[8 * AP + 4];
            #pragma unroll
            for (int nt = 0; nt < 8; nt++) {
                const uint32_t* br = Bu + (k0 + tig) * BP + nt * 8 + gid;
                const uint32_t b0 = br[0];
                const uint32_t b1r = br[4 * BP];
                mma_tf32(acc[nt], a0, a1, a2, a3, b0, b1r);
            }
        }

        // ---- Epilogue: bias + ELU + dot(W2), 4-lane shfl reduce, sigmoid ----
        float p0 = 0.f, p1 = 0.f;
        #pragma unroll
        for (int nt = 0; nt < 8; nt++) {
            const int n = nt * 8 + 2 * tig;
            const float bb0 = b1s[n], bb1 = b1s[n + 1];
            const float ww0 = w2s[n], ww1 = w2s[n + 1];
            float x;
            x = acc[nt][0] + bb0; p0 = fmaf(x > 0.f ? x : (__expf(x) - 1.f), ww0, p0);
            x = acc[nt][1] + bb1; p0 = fmaf(x > 0.f ? x : (__expf(x) - 1.f), ww1, p0);
            x = acc[nt][2] + bb0; p1 = fmaf(x > 0.f ? x : (__expf(x) - 1.f), ww0, p1);
            x = acc[nt][3] + bb1; p1 = fmaf(x > 0.f ? x : (__expf(x) - 1.f), ww1, p1);
        }
        p0 += __shfl_xor_sync(0xffffffffu, p0, 1);
        p0 += __shfl_xor_sync(0xffffffffu, p0, 2);
        p1 += __shfl_xor_sync(0xffffffffu, p1, 1);
        p1 += __shfl_xor_sync(0xffffffffu, p1, 2);
        if (tig == 0) {
            out[e0 + wb + gid]     = 1.0f / (1.0f + __expf(-(p0 + b2v)));
            out[e0 + wb + gid + 8] = 1.0f / (1.0f + __expf(-(p1 + b2v)));
        }
        __syncwarp();   // all A-frag reads done before next tile's gather stores
    }
}

extern "C" void kernel_launch(void* const* d_in, const int* in_sizes, int n_in,
                              void* d_out, int out_size) {
    const float* z_in   = (const float*)d_in[0];
    const float* z_out  = (const float*)d_in[1];
    const float* z_self = (const float*)d_in[2];
    const int*   eidx   = (const int*)d_in[3];
    const float* W1     = (const float*)d_in[4];
    const float* b1     = (const float*)d_in[5];
    const float* W2     = (const float*)d_in[6];
    const float* b2     = (const float*)d_in[7];
    float*       outp   = (float*)d_out;

    prep_kernel<<<NN * CC / 4 / 256, 256>>>(z_in, z_out, z_self);

    const int smem_bytes = SMEM_FLOATS * (int)sizeof(float);   // 69120
    cudaFuncSetAttribute(gemm_kernel,
                         cudaFuncAttributeMaxDynamicSharedMemorySize, smem_bytes);
    gemm_kernel<<<MAIN_GRID, MAIN_THREADS, smem_bytes>>>(eidx, W1, b1, W2, b2, outp);
}

// round 5
// speedup vs baseline: 2.1969x; 1.2044x over previous
#include <cuda_runtime.h>
#include <math.h>
#include <stdint.h>

#define NN 100000
#define CC 128
#define EE 600000
#define HH 64
#define TILE 128
#define NTILES ((EE + TILE - 1) / TILE)   // 4688 (last tile half)
#define MAIN_GRID 304                      // 152 SMs * 2 persistent
#define MAIN_THREADS 256

#define AP 132                  // As pitch (floats): 128 + 4 pad

// SMEM float offsets
#define OFF_A  0                // 128*132 = 16896
#define OFF_BP 16896            // packed B frags: 16*4*32*4 = 8192
#define OFF_B1 25088            // 64
#define OFF_W2 25152            // 64
#define SMEM_FLOATS 25216       // 100864 bytes

// Scratch node tables: v1 = z_out + z_self, v2 = z_in + z_self
__device__ float g_v1[(size_t)NN * CC];
__device__ float g_v2[(size_t)NN * CC];

__global__ void prep_kernel(const float* __restrict__ z_in,
                            const float* __restrict__ z_out,
                            const float* __restrict__ z_self) {
    int i = blockIdx.x * blockDim.x + threadIdx.x;
    const float4* zi = (const float4*)z_in;
    const float4* zo = (const float4*)z_out;
    const float4* zs = (const float4*)z_self;
    float4* v1 = (float4*)g_v1;
    float4* v2 = (float4*)g_v2;
    float4 s = zs[i];
    float4 a = zo[i];
    float4 b = zi[i];
    float4 r1, r2;
    r1.x = a.x + s.x; r1.y = a.y + s.y; r1.z = a.z + s.z; r1.w = a.w + s.w;
    r2.x = b.x + s.x; r2.y = b.y + s.y; r2.z = b.z + s.z; r2.w = b.w + s.w;
    v1[i] = r1;
    v2[i] = r2;
}

__device__ __forceinline__ uint32_t f2tf32(float f) {
    uint32_t u;
    asm("cvt.rna.tf32.f32 %0, %1;" : "=r"(u) : "f"(f));
    return u;
}

__device__ __forceinline__ void mma_tf32(float* c,
                                         uint32_t a0, uint32_t a1, uint32_t a2, uint32_t a3,
                                         uint32_t b0, uint32_t b1) {
    asm volatile(
        "mma.sync.aligned.m16n8k8.row.col.f32.tf32.tf32.f32 "
        "{%0,%1,%2,%3}, {%4,%5,%6,%7}, {%8,%9}, {%0,%1,%2,%3};"
        : "+f"(c[0]), "+f"(c[1]), "+f"(c[2]), "+f"(c[3])
        : "r"(a0), "r"(a1), "r"(a2), "r"(a3), "r"(b0), "r"(b1));
}

// Fused gather + GEMM (tf32 mma.sync) + ELU + GEMV + sigmoid.
// 8 warps/block; warp w owns 16 edges of the 128-edge tile and its own 16
// rows of As -> tile loop is completely barrier-free.
// B (W1^T) is pre-packed per-lane into exact mma fragment order:
//   Bp[((ks*4 + nt2)*32 + lane)] = { b0(2nt2), b1(2nt2), b0(2nt2+1), b1(2nt2+1) }
// so the k-loop does one conflict-free LDS.128 per (ks, nt-pair).
__global__ __launch_bounds__(MAIN_THREADS, 1)
void gemm_kernel(const int* __restrict__ eidx,
                 const float* __restrict__ W1,
                 const float* __restrict__ b1,
                 const float* __restrict__ W2,
                 const float* __restrict__ b2,
                 float* __restrict__ out)
{
    extern __shared__ float smem[];
    uint32_t* Au  = (uint32_t*)(smem + OFF_A);
    uint4*    Bp  = (uint4*)(smem + OFF_BP);
    float*    b1s = smem + OFF_B1;
    float*    w2s = smem + OFF_W2;

    const int tid  = threadIdx.x;
    const int lane = tid & 31;
    const int warp = tid >> 5;
    const int gid  = lane >> 2;   // 0..7
    const int tig  = lane & 3;    // 0..3
    const int wb   = warp * 16;   // A-row base for this warp

    // ---- Stage packed-B frags + vectors, once per persistent block ----
    // i indexes (ks, nt2, lane'): each thread materializes the 4-frag bundle
    // belonging to lane' = i&31 (layout depends only on lane within warp).
    for (int i = tid; i < 16 * 4 * 32; i += MAIN_THREADS) {
        const int l   = i & 31;
        const int nt2 = (i >> 5) & 3;
        const int ks  = i >> 7;
        const int g   = l >> 2;
        const int t   = l & 3;
        const int k0  = ks * 8;
        const int n0  = nt2 * 16 + g;     // nt = 2*nt2   -> col n0
        const int n1  = n0 + 8;           // nt = 2*nt2+1 -> col n0+8
        uint4 v;
        v.x = f2tf32(W1[(k0 + t) * HH + n0]);
        v.y = f2tf32(W1[(k0 + t + 4) * HH + n0]);
        v.z = f2tf32(W1[(k0 + t) * HH + n1]);
        v.w = f2tf32(W1[(k0 + t + 4) * HH + n1]);
        Bp[i] = v;
    }
    if (tid < HH) { b1s[tid] = b1[tid]; w2s[tid] = W2[tid]; }
    const float b2v = b2[0];
    __syncthreads();

    const int* srcI = eidx;
    const int* dstI = eidx + EE;

    for (int tile = blockIdx.x; tile < NTILES; tile += MAIN_GRID) {
        const int e0 = tile * TILE;
        const int ebase = e0 + wb;

        // ---- Gather + product + tf32 store into As[m][k] (pitch AP) ----
        {
            int eS = ebase + (lane & 15);
            if (eS >= EE) eS = EE - 1;            // tail: duplicate, store guarded
            const int my = (lane < 16) ? srcI[eS] : dstI[eS];
            #pragma unroll 4
            for (int i = 0; i < 16; i++) {
                const int src = __shfl_sync(0xffffffffu, my, i);
                const int dst = __shfl_sync(0xffffffffu, my, 16 + i);
                float4 a = *(const float4*)(g_v1 + (size_t)src * CC + lane * 4);
                float4 b = *(const float4*)(g_v2 + (size_t)dst * CC + lane * 4);
                uint4 p;
                p.x = f2tf32(a.x * b.x);
                p.y = f2tf32(a.y * b.y);
                p.z = f2tf32(a.z * b.z);
                p.w = f2tf32(a.w * b.w);
                *(uint4*)(Au + (wb + i) * AP + lane * 4) = p;   // STS.128
            }
        }
        __syncwarp();

        // ---- GEMM: D[16x64] per warp = A[16x128] x B[128x64] ----
        float acc[8][4];
        #pragma unroll
        for (int nt = 0; nt < 8; nt++)
            #pragma unroll
            for (int j = 0; j < 4; j++) acc[nt][j] = 0.f;

        #pragma unroll 4
        for (int ks = 0; ks < 16; ks++) {
            const int k0 = ks * 8;
            const uint32_t* ar = Au + (wb + gid) * AP + k0 + tig;
            const uint32_t a0 = ar[0];
            const uint32_t a2 = ar[4];
            const uint32_t a1 = ar[8 * AP];
            const uint32_t a3 = ar[8 * AP + 4];
            #pragma unroll
            for (int nt2 = 0; nt2 < 4; nt2++) {
                const uint4 bf = Bp[(ks * 4 + nt2) * 32 + lane];
                mma_tf32(acc[2 * nt2],     a0, a1, a2, a3, bf.x, bf.y);
                mma_tf32(acc[2 * nt2 + 1], a0, a1, a2, a3, bf.z, bf.w);
            }
        }

        // ---- Epilogue: bias + ELU + dot(W2), 4-lane shfl reduce, sigmoid ----
        float p0 = 0.f, p1 = 0.f;
        #pragma unroll
        for (int nt = 0; nt < 8; nt++) {
            const int n = nt * 8 + 2 * tig;
            const float bb0 = b1s[n], bb1 = b1s[n + 1];
            const float ww0 = w2s[n], ww1 = w2s[n + 1];
            float x;
            x = acc[nt][0] + bb0; p0 = fmaf(x > 0.f ? x : (__expf(x) - 1.f), ww0, p0);
            x = acc[nt][1] + bb1; p0 = fmaf(x > 0.f ? x : (__expf(x) - 1.f), ww1, p0);
            x = acc[nt][2] + bb0; p1 = fmaf(x > 0.f ? x : (__expf(x) - 1.f), ww0, p1);
            x = acc[nt][3] + bb1; p1 = fmaf(x > 0.f ? x : (__expf(x) - 1.f), ww1, p1);
        }
        p0 += __shfl_xor_sync(0xffffffffu, p0, 1);
        p0 += __shfl_xor_sync(0xffffffffu, p0, 2);
        p1 += __shfl_xor_sync(0xffffffffu, p1, 1);
        p1 += __shfl_xor_sync(0xffffffffu, p1, 2);
        if (tig == 0) {
            const int eo = ebase + gid;
            if (eo < EE)     out[eo]     = 1.0f / (1.0f + __expf(-(p0 + b2v)));
            if (eo + 8 < EE) out[eo + 8] = 1.0f / (1.0f + __expf(-(p1 + b2v)));
        }
        __syncwarp();   // A-frag reads done before next tile's gather stores
    }
}

extern "C" void kernel_launch(void* const* d_in, const int* in_sizes, int n_in,
                              void* d_out, int out_size) {
    const float* z_in   = (const float*)d_in[0];
    const float* z_out  = (const float*)d_in[1];
    const float* z_self = (const float*)d_in[2];
    const int*   eidx   = (const int*)d_in[3];
    const float* W1     = (const float*)d_in[4];
    const float* b1     = (const float*)d_in[5];
    const float* W2     = (const float*)d_in[6];
    const float* b2     = (const float*)d_in[7];
    float*       outp   = (float*)d_out;

    prep_kernel<<<NN * CC / 4 / 256, 256>>>(z_in, z_out, z_self);

    const int smem_bytes = SMEM_FLOATS * (int)sizeof(float);   // 100864
    cudaFuncSetAttribute(gemm_kernel,
                         cudaFuncAttributeMaxDynamicSharedMemorySize, smem_bytes);
    gemm_kernel<<<MAIN_GRID, MAIN_THREADS, smem_bytes>>>(eidx, W1, b1, W2, b2, outp);
}

// round 6
// speedup vs baseline: 3.1256x; 1.4228x over previous
#include <cuda_runtime.h>
#include <math.h>
#include <stdint.h>

#define NN 100000
#define CC 128
#define EE 600000
#define HH 64
#define TILE 128
#define NTILES ((EE + TILE - 1) / TILE)   // 4688 (last tile half)
#define MAIN_GRID 456                      // 152 SMs * 3 persistent
#define MAIN_THREADS 256

#define APW 68                  // A pitch in 32-bit words (bf16x2 units): 64 + 4 pad

// SMEM float offsets
#define OFF_A  0                // 128*68 = 8704 words
#define OFF_BP 8704             // packed B frags: 8*4*32 uint4 = 4096 words
#define OFF_B1 12800            // 64
#define OFF_W2 12864            // 64
#define SMEM_FLOATS 12928       // 51712 bytes

// Scratch node tables: v1 = z_out + z_self, v2 = z_in + z_self
__device__ float g_v1[(size_t)NN * CC];
__device__ float g_v2[(size_t)NN * CC];

__global__ void prep_kernel(const float* __restrict__ z_in,
                            const float* __restrict__ z_out,
                            const float* __restrict__ z_self) {
    int i = blockIdx.x * blockDim.x + threadIdx.x;
    const float4* zi = (const float4*)z_in;
    const float4* zo = (const float4*)z_out;
    const float4* zs = (const float4*)z_self;
    float4* v1 = (float4*)g_v1;
    float4* v2 = (float4*)g_v2;
    float4 s = zs[i];
    float4 a = zo[i];
    float4 b = zi[i];
    float4 r1, r2;
    r1.x = a.x + s.x; r1.y = a.y + s.y; r1.z = a.z + s.z; r1.w = a.w + s.w;
    r2.x = b.x + s.x; r2.y = b.y + s.y; r2.z = b.z + s.z; r2.w = b.w + s.w;
    v1[i] = r1;
    v2[i] = r2;
}

// pack two f32 -> bf16x2 (lo = first arg, hi = second arg)
__device__ __forceinline__ uint32_t f2bf2(float lo, float hi) {
    uint32_t r;
    asm("cvt.rn.bf16x2.f32 %0, %1, %2;" : "=r"(r) : "f"(hi), "f"(lo));
    return r;
}

__device__ __forceinline__ void mma_bf16(float* c,
                                         uint32_t a0, uint32_t a1, uint32_t a2, uint32_t a3,
                                         uint32_t b0, uint32_t b1) {
    asm volatile(
        "mma.sync.aligned.m16n8k16.row.col.f32.bf16.bf16.f32 "
        "{%0,%1,%2,%3}, {%4,%5,%6,%7}, {%8,%9}, {%0,%1,%2,%3};"
        : "+f"(c[0]), "+f"(c[1]), "+f"(c[2]), "+f"(c[3])
        : "r"(a0), "r"(a1), "r"(a2), "r"(a3), "r"(b0), "r"(b1));
}

// Fused gather + GEMM (bf16 m16n8k16 mma.sync, fp32 accum) + ELU + GEMV + sigmoid.
// 8 warps/block; warp w owns 16 edges of the 128-edge tile and its own 16
// rows of As -> tile loop is completely barrier-free.
// B (W1^T) pre-packed per-lane in exact fragment order:
//   Bp[(ks*4+nt2)*32+lane] = {b0(2nt2), b1(2nt2), b0(2nt2+1), b1(2nt2+1)}
__global__ __launch_bounds__(MAIN_THREADS, 3)
void gemm_kernel(const int* __restrict__ eidx,
                 const float* __restrict__ W1,
                 const float* __restrict__ b1,
                 const float* __restrict__ W2,
                 const float* __restrict__ b2,
                 float* __restrict__ out)
{
    extern __shared__ float smem[];
    uint32_t* Au  = (uint32_t*)(smem + OFF_A);
    uint4*    Bp  = (uint4*)(smem + OFF_BP);
    float*    b1s = smem + OFF_B1;
    float*    w2s = smem + OFF_W2;

    const int tid  = threadIdx.x;
    const int lane = tid & 31;
    const int warp = tid >> 5;
    const int gid  = lane >> 2;   // 0..7
    const int tig  = lane & 3;    // 0..3
    const int wb   = warp * 16;   // A-row base for this warp

    // ---- Stage packed-B frags (bf16) + vectors, once per persistent block ----
    for (int i = tid; i < 8 * 4 * 32; i += MAIN_THREADS) {
        const int l   = i & 31;
        const int nt2 = (i >> 5) & 3;
        const int ks  = i >> 7;
        const int g   = l >> 2;
        const int t   = l & 3;
        const int k0  = ks * 16;
        const int n0  = nt2 * 16 + g;     // nt = 2*nt2
        const int n1  = n0 + 8;           // nt = 2*nt2+1
        uint4 v;
        v.x = f2bf2(W1[(k0 + 2 * t) * HH + n0],     W1[(k0 + 2 * t + 1) * HH + n0]);
        v.y = f2bf2(W1[(k0 + 2 * t + 8) * HH + n0], W1[(k0 + 2 * t + 9) * HH + n0]);
        v.z = f2bf2(W1[(k0 + 2 * t) * HH + n1],     W1[(k0 + 2 * t + 1) * HH + n1]);
        v.w = f2bf2(W1[(k0 + 2 * t + 8) * HH + n1], W1[(k0 + 2 * t + 9) * HH + n1]);
        Bp[i] = v;
    }
    if (tid < HH) { b1s[tid] = b1[tid]; w2s[tid] = W2[tid]; }
    const float b2v = b2[0];
    __syncthreads();

    const int* srcI = eidx;
    const int* dstI = eidx + EE;

    for (int tile = blockIdx.x; tile < NTILES; tile += MAIN_GRID) {
        const int e0 = tile * TILE;
        const int ebase = e0 + wb;

        // ---- Gather + product (f32) + bf16x2 store into As[m] (pitch APW) ----
        {
            int eS = ebase + (lane & 15);
            if (eS >= EE) eS = EE - 1;            // tail: duplicate, store guarded
            const int my = (lane < 16) ? srcI[eS] : dstI[eS];
            #pragma unroll 8
            for (int i = 0; i < 16; i++) {
                const int src = __shfl_sync(0xffffffffu, my, i);
                const int dst = __shfl_sync(0xffffffffu, my, 16 + i);
                float4 a = *(const float4*)(g_v1 + (size_t)src * CC + lane * 4);
                float4 b = *(const float4*)(g_v2 + (size_t)dst * CC + lane * 4);
                uint2 p;
                p.x = f2bf2(a.x * b.x, a.y * b.y);
                p.y = f2bf2(a.z * b.z, a.w * b.w);
                *(uint2*)(Au + (wb + i) * APW + 2 * lane) = p;   // STS.64
            }
        }
        __syncwarp();

        // ---- GEMM: D[16x64] per warp = A[16x128] x B[128x64], k16 steps ----
        float acc[8][4];
        #pragma unroll
        for (int nt = 0; nt < 8; nt++)
            #pragma unroll
            for (int j = 0; j < 4; j++) acc[nt][j] = 0.f;

        #pragma unroll
        for (int ks = 0; ks < 8; ks++) {
            const uint32_t* ar = Au + (wb + gid) * APW + 8 * ks + tig;
            const uint32_t a0 = ar[0];            // row gid,   k lo pair
            const uint32_t a2 = ar[4];            // row gid,   k hi pair
            const uint32_t a1 = ar[8 * APW];      // row gid+8, k lo pair
            const uint32_t a3 = ar[8 * APW + 4];  // row gid+8, k hi pair
            #pragma unroll
            for (int nt2 = 0; nt2 < 4; nt2++) {
                const uint4 bf = Bp[(ks * 4 + nt2) * 32 + lane];
                mma_bf16(acc[2 * nt2],     a0, a1, a2, a3, bf.x, bf.y);
                mma_bf16(acc[2 * nt2 + 1], a0, a1, a2, a3, bf.z, bf.w);
            }
        }

        // ---- Epilogue: bias + ELU + dot(W2), 4-lane shfl reduce, sigmoid ----
        float p0 = 0.f, p1 = 0.f;
        #pragma unroll
        for (int nt = 0; nt < 8; nt++) {
            const int n = nt * 8 + 2 * tig;
            const float bb0 = b1s[n], bb1 = b1s[n + 1];
            const float ww0 = w2s[n], ww1 = w2s[n + 1];
            float x;
            x = acc[nt][0] + bb0; p0 = fmaf(x > 0.f ? x : (__expf(x) - 1.f), ww0, p0);
            x = acc[nt][1] + bb1; p0 = fmaf(x > 0.f ? x : (__expf(x) - 1.f), ww1, p0);
            x = acc[nt][2] + bb0; p1 = fmaf(x > 0.f ? x : (__expf(x) - 1.f), ww0, p1);
            x = acc[nt][3] + bb1; p1 = fmaf(x > 0.f ? x : (__expf(x) - 1.f), ww1, p1);
        }
        p0 += __shfl_xor_sync(0xffffffffu, p0, 1);
        p0 += __shfl_xor_sync(0xffffffffu, p0, 2);
        p1 += __shfl_xor_sync(0xffffffffu, p1, 1);
        p1 += __shfl_xor_sync(0xffffffffu, p1, 2);
        if (tig == 0) {
            const int eo = ebase + gid;
            if (eo < EE)     out[eo]     = 1.0f / (1.0f + __expf(-(p0 + b2v)));
            if (eo + 8 < EE) out[eo + 8] = 1.0f / (1.0f + __expf(-(p1 + b2v)));
        }
        __syncwarp();   // A reads done before next tile's gather stores
    }
}

extern "C" void kernel_launch(void* const* d_in, const int* in_sizes, int n_in,
                              void* d_out, int out_size) {
    const float* z_in   = (const float*)d_in[0];
    const float* z_out  = (const float*)d_in[1];
    const float* z_self = (const float*)d_in[2];
    const int*   eidx   = (const int*)d_in[3];
    const float* W1     = (const float*)d_in[4];
    const float* b1     = (const float*)d_in[5];
    const float* W2     = (const float*)d_in[6];
    const float* b2     = (const float*)d_in[7];
    float*       outp   = (float*)d_out;

    prep_kernel<<<NN * CC / 4 / 256, 256>>>(z_in, z_out, z_self);

    const int smem_bytes = SMEM_FLOATS * (int)sizeof(float);   // 51712
    cudaFuncSetAttribute(gemm_kernel,
                         cudaFuncAttributeMaxDynamicSharedMemorySize, smem_bytes);
    gemm_kernel<<<MAIN_GRID, MAIN_THREADS, smem_bytes>>>(eidx, W1, b1, W2, b2, outp);
}

// round 7
// speedup vs baseline: 3.3504x; 1.0719x over previous
#include <cuda_runtime.h>
#include <cuda_fp16.h>
#include <math.h>
#include <stdint.h>

#define NN 100000
#define CC 128
#define EE 600000
#define HH 64
#define TILE 128
#define NTILES ((EE + TILE - 1) / TILE)   // 4688 (last tile half)
#define MAIN_GRID 456                      // 152 SMs * 3 persistent
#define MAIN_THREADS 256

#define APW 68                  // A pitch in 32-bit words (fp16x2 units): 64 + 4 pad

// SMEM float offsets
#define OFF_A  0                // 128*68 = 8704 words
#define OFF_BP 8704             // packed B frags: 8*4*32 uint4 = 4096 words
#define OFF_B1 12800            // 64
#define OFF_W2 12864            // 64
#define SMEM_FLOATS 12928       // 51712 bytes

// Node tables in fp16: v1 = z_out + z_self, v2 = z_in + z_self (25.6 MB each).
// uint4 units: one uint4 = 8 halves; row = CC/8 = 16 uint4.
__device__ uint4 g_v1h[(size_t)NN * CC / 8];
__device__ uint4 g_v2h[(size_t)NN * CC / 8];

// pack two f32 -> f16x2 (lo = first arg, hi = second arg)
__device__ __forceinline__ uint32_t f2h2(float lo, float hi) {
    uint32_t r;
    asm("cvt.rn.f16x2.f32 %0, %1, %2;" : "=r"(r) : "f"(hi), "f"(lo));
    return r;
}

__global__ void prep_kernel(const float* __restrict__ z_in,
                            const float* __restrict__ z_out,
                            const float* __restrict__ z_self) {
    const int i = blockIdx.x * blockDim.x + threadIdx.x;   // 8 channels / thread
    const float4* zi = (const float4*)z_in;
    const float4* zo = (const float4*)z_out;
    const float4* zs = (const float4*)z_self;
    const float4 s0 = zs[2 * i],     s1 = zs[2 * i + 1];
    const float4 a0 = zo[2 * i],     a1 = zo[2 * i + 1];
    const float4 b0 = zi[2 * i],     b1 = zi[2 * i + 1];
    uint4 o1, o2;
    o1.x = f2h2(a0.x + s0.x, a0.y + s0.y);
    o1.y = f2h2(a0.z + s0.z, a0.w + s0.w);
    o1.z = f2h2(a1.x + s1.x, a1.y + s1.y);
    o1.w = f2h2(a1.z + s1.z, a1.w + s1.w);
    o2.x = f2h2(b0.x + s0.x, b0.y + s0.y);
    o2.y = f2h2(b0.z + s0.z, b0.w + s0.w);
    o2.z = f2h2(b1.x + s1.x, b1.y + s1.y);
    o2.w = f2h2(b1.z + s1.z, b1.w + s1.w);
    g_v1h[i] = o1;
    g_v2h[i] = o2;
}

__device__ __forceinline__ void mma_f16(float* c,
                                        uint32_t a0, uint32_t a1, uint32_t a2, uint32_t a3,
                                        uint32_t b0, uint32_t b1) {
    asm volatile(
        "mma.sync.aligned.m16n8k16.row.col.f32.f16.f16.f32 "
        "{%0,%1,%2,%3}, {%4,%5,%6,%7}, {%8,%9}, {%0,%1,%2,%3};"
        : "+f"(c[0]), "+f"(c[1]), "+f"(c[2]), "+f"(c[3])
        : "r"(a0), "r"(a1), "r"(a2), "r"(a3), "r"(b0), "r"(b1));
}

// Fused gather + GEMM (fp16 m16n8k16 mma.sync, fp32 accum) + ELU + GEMV + sigmoid.
// 8 warps/block; warp w owns 16 edges of the 128-edge tile -> barrier-free.
__global__ __launch_bounds__(MAIN_THREADS, 3)
void gemm_kernel(const int* __restrict__ eidx,
                 const float* __restrict__ W1,
                 const float* __restrict__ b1,
                 const float* __restrict__ W2,
                 const float* __restrict__ b2,
                 float* __restrict__ out)
{
    extern __shared__ float smem[];
    uint32_t* Au  = (uint32_t*)(smem + OFF_A);
    uint4*    Bp  = (uint4*)(smem + OFF_BP);
    float*    b1s = smem + OFF_B1;
    float*    w2s = smem + OFF_W2;

    const int tid  = threadIdx.x;
    const int lane = tid & 31;
    const int warp = tid >> 5;
    const int gid  = lane >> 2;   // 0..7
    const int tig  = lane & 3;    // 0..3
    const int wb   = warp * 16;   // A-row base for this warp
    const int lw   = lane & 15;

    // ---- Stage packed-B frags (fp16) + vectors, once per persistent block ----
    for (int i = tid; i < 8 * 4 * 32; i += MAIN_THREADS) {
        const int l   = i & 31;
        const int nt2 = (i >> 5) & 3;
        const int ks  = i >> 7;
        const int g   = l >> 2;
        const int t   = l & 3;
        const int k0  = ks * 16;
        const int n0  = nt2 * 16 + g;     // nt = 2*nt2
        const int n1  = n0 + 8;           // nt = 2*nt2+1
        uint4 v;
        v.x = f2h2(W1[(k0 + 2 * t) * HH + n0],     W1[(k0 + 2 * t + 1) * HH + n0]);
        v.y = f2h2(W1[(k0 + 2 * t + 8) * HH + n0], W1[(k0 + 2 * t + 9) * HH + n0]);
        v.z = f2h2(W1[(k0 + 2 * t) * HH + n1],     W1[(k0 + 2 * t + 1) * HH + n1]);
        v.w = f2h2(W1[(k0 + 2 * t + 8) * HH + n1], W1[(k0 + 2 * t + 9) * HH + n1]);
        Bp[i] = v;
    }
    if (tid < HH) { b1s[tid] = b1[tid]; w2s[tid] = W2[tid]; }
    const float b2v = b2[0];
    __syncthreads();

    const int* srcI = eidx;
    const int* dstI = eidx + EE;

    for (int tile = blockIdx.x; tile < NTILES; tile += MAIN_GRID) {
        const int e0 = tile * TILE;
        const int ebase = e0 + wb;

        // ---- Gather: lanes 0-15 load v1[src] row (16B each), lanes 16-31
        //      load v2[dst]; shfl.xor(16) exchange; f16x2 product; STS.128. ----
        {
            int eS = ebase + lw;
            if (eS >= EE) eS = EE - 1;            // tail: duplicate, store guarded
            const int my = (lane < 16) ? srcI[eS] : dstI[eS];
            const uint4* tab = (lane < 16) ? g_v1h : g_v2h;
            #pragma unroll 8
            for (int i = 0; i < 16; i++) {
                const int sidx = __shfl_sync(0xffffffffu, my, i);
                const int didx = __shfl_sync(0xffffffffu, my, 16 + i);
                const int idx  = (lane < 16) ? sidx : didx;
                const uint4 va = tab[(size_t)idx * (CC / 8) + lw];
                uint4 vb;
                vb.x = __shfl_xor_sync(0xffffffffu, va.x, 16);
                vb.y = __shfl_xor_sync(0xffffffffu, va.y, 16);
                vb.z = __shfl_xor_sync(0xffffffffu, va.z, 16);
                vb.w = __shfl_xor_sync(0xffffffffu, va.w, 16);
                if (lane < 16) {
                    uint4 p;
                    asm("mul.rn.f16x2 %0, %1, %2;" : "=r"(p.x) : "r"(va.x), "r"(vb.x));
                    asm("mul.rn.f16x2 %0, %1, %2;" : "=r"(p.y) : "r"(va.y), "r"(vb.y));
                    asm("mul.rn.f16x2 %0, %1, %2;" : "=r"(p.z) : "r"(va.z), "r"(vb.z));
                    asm("mul.rn.f16x2 %0, %1, %2;" : "=r"(p.w) : "r"(va.w), "r"(vb.w));
                    *(uint4*)(Au + (wb + i) * APW + lw * 4) = p;
                }
            }
        }
        __syncwarp();

        // ---- GEMM: D[16x64] per warp = A[16x128] x B[128x64], k16 steps ----
        float acc[8][4];
        #pragma unroll
        for (int nt = 0; nt < 8; nt++)
            #pragma unroll
            for (int j = 0; j < 4; j++) acc[nt][j] = 0.f;

        #pragma unroll
        for (int ks = 0; ks < 8; ks++) {
            const uint32_t* ar = Au + (wb + gid) * APW + 8 * ks + tig;
            const uint32_t a0 = ar[0];            // row gid,   k lo pair
            const uint32_t a2 = ar[4];            // row gid,   k hi pair
            const uint32_t a1 = ar[8 * APW];      // row gid+8, k lo pair
            const uint32_t a3 = ar[8 * APW + 4];  // row gid+8, k hi pair
            #pragma unroll
            for (int nt2 = 0; nt2 < 4; nt2++) {
                const uint4 bf = Bp[(ks * 4 + nt2) * 32 + lane];
                mma_f16(acc[2 * nt2],     a0, a1, a2, a3, bf.x, bf.y);
                mma_f16(acc[2 * nt2 + 1], a0, a1, a2, a3, bf.z, bf.w);
            }
        }

        // ---- Epilogue: bias + ELU + dot(W2), 4-lane shfl reduce, sigmoid ----
        float p0 = 0.f, p1 = 0.f;
        #pragma unroll
        for (int nt = 0; nt < 8; nt++) {
            const int n = nt * 8 + 2 * tig;
            const float bb0 = b1s[n], bb1 = b1s[n + 1];
            const float ww0 = w2s[n], ww1 = w2s[n + 1];
            float x;
            x = acc[nt][0] + bb0; p0 = fmaf(x > 0.f ? x : (__expf(x) - 1.f), ww0, p0);
            x = acc[nt][1] + bb1; p0 = fmaf(x > 0.f ? x : (__expf(x) - 1.f), ww1, p0);
            x = acc[nt][2] + bb0; p1 = fmaf(x > 0.f ? x : (__expf(x) - 1.f), ww0, p1);
            x = acc[nt][3] + bb1; p1 = fmaf(x > 0.f ? x : (__expf(x) - 1.f), ww1, p1);
        }
        p0 += __shfl_xor_sync(0xffffffffu, p0, 1);
        p0 += __shfl_xor_sync(0xffffffffu, p0, 2);
        p1 += __shfl_xor_sync(0xffffffffu, p1, 1);
        p1 += __shfl_xor_sync(0xffffffffu, p1, 2);
        if (tig == 0) {
            const int eo = ebase + gid;
            if (eo < EE)     out[eo]     = 1.0f / (1.0f + __expf(-(p0 + b2v)));
            if (eo + 8 < EE) out[eo + 8] = 1.0f / (1.0f + __expf(-(p1 + b2v)));
        }
        __syncwarp();   // A reads done before next tile's gather stores
    }
}

extern "C" void kernel_launch(void* const* d_in, const int* in_sizes, int n_in,
                              void* d_out, int out_size) {
    const float* z_in   = (const float*)d_in[0];
    const float* z_out  = (const float*)d_in[1];
    const float* z_self = (const float*)d_in[2];
    const int*   eidx   = (const int*)d_in[3];
    const float* W1     = (const float*)d_in[4];
    const float* b1     = (const float*)d_in[5];
    const float* W2     = (const float*)d_in[6];
    const float* b2     = (const float*)d_in[7];
    float*       outp   = (float*)d_out;

    // 8 channels per thread: NN*CC/8 threads exactly
    prep_kernel<<<NN * CC / 8 / 256, 256>>>(z_in, z_out, z_self);

    const int smem_bytes = SMEM_FLOATS * (int)sizeof(float);   // 51712
    cudaFuncSetAttribute(gemm_kernel,
                         cudaFuncAttributeMaxDynamicSharedMemorySize, smem_bytes);
    gemm_kernel<<<MAIN_GRID, MAIN_THREADS, smem_bytes>>>(eidx, W1, b1, W2, b2, outp);
}

// round 8
// speedup vs baseline: 3.4080x; 1.0172x over previous
#include <cuda_runtime.h>
#include <cuda_fp16.h>
#include <math.h>
#include <stdint.h>

#define NN 100000
#define CC 128
#define EE 600000
#define HH 64
#define TILE 128
#define NTILES ((EE + TILE - 1) / TILE)   // 4688 (last tile half)
#define MAIN_GRID 456                      // 152 SMs * 3 persistent
#define MAIN_THREADS 256

#define APW 68                  // A pitch in 32-bit words (fp16x2 units): 64 + 4 pad

// SMEM float offsets
#define OFF_A   0               // 128*68 = 8704 words
#define OFF_BP  8704            // packed B frags: 8*4*32 uint4 = 4096 words
#define OFF_B1  12800           // 64
#define OFF_W2  12864           // 64
#define OFF_RED 12928           // 8 warps * 32 partials = 256
#define SMEM_FLOATS 13184       // 52736 bytes

// Node tables in fp16: v1 = z_out + z_self, v2 = z_in + z_self (25.6 MB each).
__device__ uint4 g_v1h[(size_t)NN * CC / 8];
__device__ uint4 g_v2h[(size_t)NN * CC / 8];

__device__ __forceinline__ uint32_t f2h2(float lo, float hi) {
    uint32_t r;
    asm("cvt.rn.f16x2.f32 %0, %1, %2;" : "=r"(r) : "f"(hi), "f"(lo));
    return r;
}

__global__ void prep_kernel(const float* __restrict__ z_in,
                            const float* __restrict__ z_out,
                            const float* __restrict__ z_self) {
    const int i = blockIdx.x * blockDim.x + threadIdx.x;   // 8 channels / thread
    const float4* zi = (const float4*)z_in;
    const float4* zo = (const float4*)z_out;
    const float4* zs = (const float4*)z_self;
    const float4 s0 = zs[2 * i],     s1 = zs[2 * i + 1];
    const float4 a0 = zo[2 * i],     a1 = zo[2 * i + 1];
    const float4 b0 = zi[2 * i],     b1 = zi[2 * i + 1];
    uint4 o1, o2;
    o1.x = f2h2(a0.x + s0.x, a0.y + s0.y);
    o1.y = f2h2(a0.z + s0.z, a0.w + s0.w);
    o1.z = f2h2(a1.x + s1.x, a1.y + s1.y);
    o1.w = f2h2(a1.z + s1.z, a1.w + s1.w);
    o2.x = f2h2(b0.x + s0.x, b0.y + s0.y);
    o2.y = f2h2(b0.z + s0.z, b0.w + s0.w);
    o2.z = f2h2(b1.x + s1.x, b1.y + s1.y);
    o2.w = f2h2(b1.z + s1.z, b1.w + s1.w);
    g_v1h[i] = o1;
    g_v2h[i] = o2;
}

__device__ __forceinline__ void mma_f16(float* c,
                                        uint32_t a0, uint32_t a1, uint32_t a2, uint32_t a3,
                                        uint32_t b0, uint32_t b1) {
    asm volatile(
        "mma.sync.aligned.m16n8k16.row.col.f32.f16.f16.f32 "
        "{%0,%1,%2,%3}, {%4,%5,%6,%7}, {%8,%9}, {%0,%1,%2,%3};"
        : "+f"(c[0]), "+f"(c[1]), "+f"(c[2]), "+f"(c[3])
        : "r"(a0), "r"(a1), "r"(a2), "r"(a3), "r"(b0), "r"(b1));
}

// Fused gather + GEMM (fp16 mma.sync) + ELU + GEMV + sigmoid.
// Warp PAIRS share 32 edges; each warp covers half of N (32 h-cols) and both
// m16 tiles, so every B fragment load is reused 2x and per-edge B traffic
// drops 4x vs one-warp-per-16-edges. Pair-scoped named barriers only.
__global__ __launch_bounds__(MAIN_THREADS, 3)
void gemm_kernel(const int* __restrict__ eidx,
                 const float* __restrict__ W1,
                 const float* __restrict__ b1,
                 const float* __restrict__ W2,
                 const float* __restrict__ b2,
                 float* __restrict__ out)
{
    extern __shared__ float smem[];
    uint32_t* Au  = (uint32_t*)(smem + OFF_A);
    uint4*    Bp  = (uint4*)(smem + OFF_BP);
    float*    b1s = smem + OFF_B1;
    float*    w2s = smem + OFF_W2;
    float*    red = smem + OFF_RED;

    const int tid   = threadIdx.x;
    const int lane  = tid & 31;
    const int warp  = tid >> 5;
    const int gid   = lane >> 2;   // 0..7
    const int tig   = lane & 3;    // 0..3
    const int wb    = warp * 16;   // gather row base (16 edges per warp)
    const int lw    = lane & 15;
    const int pair  = warp >> 1;   // 0..3
    const int nhalf = warp & 1;    // n-half: 0 -> cols 0..31, 1 -> 32..63
    const int pb    = pair * 32;   // pair's edge-row base within tile
    const int barid = pair + 1;

    // ---- Stage packed-B frags (fp16) + vectors, once per persistent block ----
    for (int i = tid; i < 8 * 4 * 32; i += MAIN_THREADS) {
        const int l   = i & 31;
        const int nt2 = (i >> 5) & 3;
        const int ks  = i >> 7;
        const int g   = l >> 2;
        const int t   = l & 3;
        const int k0  = ks * 16;
        const int n0  = nt2 * 16 + g;
        const int n1  = n0 + 8;
        uint4 v;
        v.x = f2h2(W1[(k0 + 2 * t) * HH + n0],     W1[(k0 + 2 * t + 1) * HH + n0]);
        v.y = f2h2(W1[(k0 + 2 * t + 8) * HH + n0], W1[(k0 + 2 * t + 9) * HH + n0]);
        v.z = f2h2(W1[(k0 + 2 * t) * HH + n1],     W1[(k0 + 2 * t + 1) * HH + n1]);
        v.w = f2h2(W1[(k0 + 2 * t + 8) * HH + n1], W1[(k0 + 2 * t + 9) * HH + n1]);
        Bp[i] = v;
    }
    if (tid < HH) { b1s[tid] = b1[tid]; w2s[tid] = W2[tid]; }
    const float b2v = b2[0];
    __syncthreads();

    const int* srcI = eidx;
    const int* dstI = eidx + EE;

    for (int tile = blockIdx.x; tile < NTILES; tile += MAIN_GRID) {
        const int e0 = tile * TILE;

        // ---- Gather own 16 edges into As rows [wb, wb+16) ----
        {
            int eS = e0 + wb + lw;
            if (eS >= EE) eS = EE - 1;            // tail: duplicate, store guarded
            const int my = (lane < 16) ? srcI[eS] : dstI[eS];
            const uint4* tab = (lane < 16) ? g_v1h : g_v2h;
            #pragma unroll 8
            for (int i = 0; i < 16; i++) {
                const int sidx = __shfl_sync(0xffffffffu, my, i);
                const int didx = __shfl_sync(0xffffffffu, my, 16 + i);
                const int idx  = (lane < 16) ? sidx : didx;
                const uint4 va = tab[(size_t)idx * (CC / 8) + lw];
                uint4 vb;
                vb.x = __shfl_xor_sync(0xffffffffu, va.x, 16);
                vb.y = __shfl_xor_sync(0xffffffffu, va.y, 16);
                vb.z = __shfl_xor_sync(0xffffffffu, va.z, 16);
                vb.w = __shfl_xor_sync(0xffffffffu, va.w, 16);
                if (lane < 16) {
                    uint4 p;
                    asm("mul.rn.f16x2 %0, %1, %2;" : "=r"(p.x) : "r"(va.x), "r"(vb.x));
                    asm("mul.rn.f16x2 %0, %1, %2;" : "=r"(p.y) : "r"(va.y), "r"(vb.y));
                    asm("mul.rn.f16x2 %0, %1, %2;" : "=r"(p.z) : "r"(va.z), "r"(vb.z));
                    asm("mul.rn.f16x2 %0, %1, %2;" : "=r"(p.w) : "r"(va.w), "r"(vb.w));
                    *(uint4*)(Au + (wb + i) * APW + lw * 4) = p;
                }
            }
        }
        asm volatile("bar.sync %0, %1;" :: "r"(barid), "r"(64) : "memory");

        // ---- GEMM: rows [pb, pb+32), n-half nhalf; B reused across 2 m-tiles ----
        float acc[2][4][4];
        #pragma unroll
        for (int mt = 0; mt < 2; mt++)
            #pragma unroll
            for (int jj = 0; jj < 4; jj++)
                #pragma unroll
                for (int c = 0; c < 4; c++) acc[mt][jj][c] = 0.f;

        #pragma unroll
        for (int ks = 0; ks < 8; ks++) {
            const uint32_t* ar0 = Au + (pb + gid) * APW + 8 * ks + tig;
            const uint32_t* ar1 = ar0 + 16 * APW;
            const uint32_t a00 = ar0[0], a02 = ar0[4];
            const uint32_t a01 = ar0[8 * APW], a03 = ar0[8 * APW + 4];
            const uint32_t a10 = ar1[0], a12 = ar1[4];
            const uint32_t a11 = ar1[8 * APW], a13 = ar1[8 * APW + 4];
            const uint4 bf0 = Bp[(ks * 4 + 2 * nhalf) * 32 + lane];
            const uint4 bf1 = Bp[(ks * 4 + 2 * nhalf + 1) * 32 + lane];
            mma_f16(acc[0][0], a00, a01, a02, a03, bf0.x, bf0.y);
            mma_f16(acc[0][1], a00, a01, a02, a03, bf0.z, bf0.w);
            mma_f16(acc[0][2], a00, a01, a02, a03, bf1.x, bf1.y);
            mma_f16(acc[0][3], a00, a01, a02, a03, bf1.z, bf1.w);
            mma_f16(acc[1][0], a10, a11, a12, a13, bf0.x, bf0.y);
            mma_f16(acc[1][1], a10, a11, a12, a13, bf0.z, bf0.w);
            mma_f16(acc[1][2], a10, a11, a12, a13, bf1.x, bf1.y);
            mma_f16(acc[1][3], a10, a11, a12, a13, bf1.z, bf1.w);
        }

        // ---- Epilogue: bias + ELU + dot(W2) over this warp's 32 n's ----
        #pragma unroll
        for (int mt = 0; mt < 2; mt++) {
            float p0 = 0.f, p1 = 0.f;
            #pragma unroll
            for (int jj = 0; jj < 4; jj++) {
                const int n = (nhalf * 4 + jj) * 8 + 2 * tig;
                const float bb0 = b1s[n], bb1 = b1s[n + 1];
                const float ww0 = w2s[n], ww1 = w2s[n + 1];
                float x;
                x = acc[mt][jj][0] + bb0; p0 = fmaf(x > 0.f ? x : (__expf(x) - 1.f), ww0, p0);
                x = acc[mt][jj][1] + bb1; p0 = fmaf(x > 0.f ? x : (__expf(x) - 1.f), ww1, p0);
                x = acc[mt][jj][2] + bb0; p1 = fmaf(x > 0.f ? x : (__expf(x) - 1.f), ww0, p1);
                x = acc[mt][jj][3] + bb1; p1 = fmaf(x > 0.f ? x : (__expf(x) - 1.f), ww1, p1);
            }
            p0 += __shfl_xor_sync(0xffffffffu, p0, 1);
            p0 += __shfl_xor_sync(0xffffffffu, p0, 2);
            p1 += __shfl_xor_sync(0xffffffffu, p1, 1);
            p1 += __shfl_xor_sync(0xffffffffu, p1, 2);
            if (tig == 0) {
                red[warp * 32 + mt * 16 + gid]     = p0;
                red[warp * 32 + mt * 16 + gid + 8] = p1;
            }
        }
        asm volatile("bar.sync %0, %1;" :: "r"(barid), "r"(64) : "memory");

        // ---- Finalize: each warp of the pair outputs 16 of the 32 edges ----
        if (lane < 16) {
            const int el = nhalf * 16 + lane;
            const float s = red[(pair * 2) * 32 + el] + red[(pair * 2 + 1) * 32 + el] + b2v;
            const int e = e0 + pb + el;
            if (e < EE) out[e] = 1.0f / (1.0f + __expf(-s));
        }
        // next gather's As writes are ordered by the post-gather bar.sync
    }
}

extern "C" void kernel_launch(void* const* d_in, const int* in_sizes, int n_in,
                              void* d_out, int out_size) {
    const float* z_in   = (const float*)d_in[0];
    const float* z_out  = (const float*)d_in[1];
    const float* z_self = (const float*)d_in[2];
    const int*   eidx   = (const int*)d_in[3];
    const float* W1     = (const float*)d_in[4];
    const float* b1     = (const float*)d_in[5];
    const float* W2     = (const float*)d_in[6];
    const float* b2     = (const float*)d_in[7];
    float*       outp   = (float*)d_out;

    prep_kernel<<<NN * CC / 8 / 256, 256>>>(z_in, z_out, z_self);

    const int smem_bytes = SMEM_FLOATS * (int)sizeof(float);   // 52736
    cudaFuncSetAttribute(gemm_kernel,
                         cudaFuncAttributeMaxDynamicSharedMemorySize, smem_bytes);
    gemm_kernel<<<MAIN_GRID, MAIN_THREADS, smem_bytes>>>(eidx, W1, b1, W2, b2, outp);
}

// round 9
// speedup vs baseline: 3.6379x; 1.0675x over previous
#include <cuda_runtime.h>
#include <cuda_fp16.h>
#include <math.h>
#include <stdint.h>

#define NN 100000
#define CC 128
#define EE 600000
#define HH 64
#define TILE 128
#define NTILES ((EE + TILE - 1) / TILE)   // 4688 (last tile half)
#define MAIN_GRID 608                      // 152 SMs * 4 persistent
#define MAIN_THREADS 256

#define APW 68                  // A pitch in 32-bit words (fp16x2 units): 64 + 4 pad

// SMEM float offsets
#define OFF_A   0               // 128*68 = 8704 words
#define OFF_BP  8704            // packed B frags: 8*4*32 uint4 = 4096 words
#define OFF_B1  12800           // 64
#define OFF_W2  12864           // 64
#define OFF_RED 12928           // 8 warps * 32 partials = 256
#define SMEM_FLOATS 13184       // 52736 bytes -> 4 blocks/SM fits (211KB)

// Node tables in fp16: v1 = z_out + z_self, v2 = z_in + z_self (25.6 MB each).
__device__ uint4 g_v1h[(size_t)NN * CC / 8];
__device__ uint4 g_v2h[(size_t)NN * CC / 8];

__device__ __forceinline__ uint32_t f2h2(float lo, float hi) {
    uint32_t r;
    asm("cvt.rn.f16x2.f32 %0, %1, %2;" : "=r"(r) : "f"(hi), "f"(lo));
    return r;
}

__global__ void prep_kernel(const float* __restrict__ z_in,
                            const float* __restrict__ z_out,
                            const float* __restrict__ z_self) {
    const int i = blockIdx.x * blockDim.x + threadIdx.x;   // 8 channels / thread
    const float4* zi = (const float4*)z_in;
    const float4* zo = (const float4*)z_out;
    const float4* zs = (const float4*)z_self;
    const float4 s0 = zs[2 * i],     s1 = zs[2 * i + 1];
    const float4 a0 = zo[2 * i],     a1 = zo[2 * i + 1];
    const float4 b0 = zi[2 * i],     b1 = zi[2 * i + 1];
    uint4 o1, o2;
    o1.x = f2h2(a0.x + s0.x, a0.y + s0.y);
    o1.y = f2h2(a0.z + s0.z, a0.w + s0.w);
    o1.z = f2h2(a1.x + s1.x, a1.y + s1.y);
    o1.w = f2h2(a1.z + s1.z, a1.w + s1.w);
    o2.x = f2h2(b0.x + s0.x, b0.y + s0.y);
    o2.y = f2h2(b0.z + s0.z, b0.w + s0.w);
    o2.z = f2h2(b1.x + s1.x, b1.y + s1.y);
    o2.w = f2h2(b1.z + s1.z, b1.w + s1.w);
    g_v1h[i] = o1;
    g_v2h[i] = o2;
}

__device__ __forceinline__ void mma_f16(float* c,
                                        uint32_t a0, uint32_t a1, uint32_t a2, uint32_t a3,
                                        uint32_t b0, uint32_t b1) {
    asm volatile(
        "mma.sync.aligned.m16n8k16.row.col.f32.f16.f16.f32 "
        "{%0,%1,%2,%3}, {%4,%5,%6,%7}, {%8,%9}, {%0,%1,%2,%3};"
        : "+f"(c[0]), "+f"(c[1]), "+f"(c[2]), "+f"(c[3])
        : "r"(a0), "r"(a1), "r"(a2), "r"(a3), "r"(b0), "r"(b1));
}

// Fused gather + GEMM (fp16 mma.sync) + ELU + GEMV + sigmoid.
// Gather is exchange-free: every lane loads matching 8B chunks of v1[src]
// and v2[dst] and multiplies locally (no shfl.xor data exchange).
// Warp PAIRS share 32 edges; each warp covers half of N and both m16 tiles.
__global__ __launch_bounds__(MAIN_THREADS, 4)
void gemm_kernel(const int* __restrict__ eidx,
                 const float* __restrict__ W1,
                 const float* __restrict__ b1,
                 const float* __restrict__ W2,
                 const float* __restrict__ b2,
                 float* __restrict__ out)
{
    extern __shared__ float smem[];
    uint32_t* Au  = (uint32_t*)(smem + OFF_A);
    uint4*    Bp  = (uint4*)(smem + OFF_BP);
    float*    b1s = smem + OFF_B1;
    float*    w2s = smem + OFF_W2;
    float*    red = smem + OFF_RED;

    const int tid   = threadIdx.x;
    const int lane  = tid & 31;
    const int warp  = tid >> 5;
    const int gid   = lane >> 2;   // 0..7
    const int tig   = lane & 3;    // 0..3
    const int wb    = warp * 16;   // gather row base (16 edges per warp)
    const int lw    = lane & 15;
    const int pair  = warp >> 1;   // 0..3
    const int nhalf = warp & 1;    // n-half: 0 -> cols 0..31, 1 -> 32..63
    const int pb    = pair * 32;   // pair's edge-row base within tile
    const int barid = pair + 1;

    // ---- Stage packed-B frags (fp16) + vectors, once per persistent block ----
    for (int i = tid; i < 8 * 4 * 32; i += MAIN_THREADS) {
        const int l   = i & 31;
        const int nt2 = (i >> 5) & 3;
        const int ks  = i >> 7;
        const int g   = l >> 2;
        const int t   = l & 3;
        const int k0  = ks * 16;
        const int n0  = nt2 * 16 + g;
        const int n1  = n0 + 8;
        uint4 v;
        v.x = f2h2(W1[(k0 + 2 * t) * HH + n0],     W1[(k0 + 2 * t + 1) * HH + n0]);
        v.y = f2h2(W1[(k0 + 2 * t + 8) * HH + n0], W1[(k0 + 2 * t + 9) * HH + n0]);
        v.z = f2h2(W1[(k0 + 2 * t) * HH + n1],     W1[(k0 + 2 * t + 1) * HH + n1]);
        v.w = f2h2(W1[(k0 + 2 * t + 8) * HH + n1], W1[(k0 + 2 * t + 9) * HH + n1]);
        Bp[i] = v;
    }
    if (tid < HH) { b1s[tid] = b1[tid]; w2s[tid] = W2[tid]; }
    const float b2v = b2[0];
    __syncthreads();

    const int* srcI = eidx;
    const int* dstI = eidx + EE;
    const uint2* t1 = (const uint2*)g_v1h;   // 32 uint2 per node row
    const uint2* t2 = (const uint2*)g_v2h;

    for (int tile = blockIdx.x; tile < NTILES; tile += MAIN_GRID) {
        const int e0 = tile * TILE;

        // ---- Gather own 16 edges into As rows [wb, wb+16) ----
        {
            int eS = e0 + wb + lw;
            if (eS >= EE) eS = EE - 1;            // tail: duplicate, discarded
            const int my = (lane < 16) ? srcI[eS] : dstI[eS];
            #pragma unroll
            for (int i = 0; i < 16; i++) {
                const int src = __shfl_sync(0xffffffffu, my, i);
                const int dst = __shfl_sync(0xffffffffu, my, 16 + i);
                const uint2 a = t1[(size_t)src * (CC / 4) + lane];
                const uint2 b = t2[(size_t)dst * (CC / 4) + lane];
                uint2 p;
                asm("mul.rn.f16x2 %0, %1, %2;" : "=r"(p.x) : "r"(a.x), "r"(b.x));
                asm("mul.rn.f16x2 %0, %1, %2;" : "=r"(p.y) : "r"(a.y), "r"(b.y));
                *(uint2*)(Au + (wb + i) * APW + lane * 2) = p;   // STS.64
            }
        }
        asm volatile("bar.sync %0, %1;" :: "r"(barid), "r"(64) : "memory");

        // ---- GEMM: rows [pb, pb+32), n-half nhalf; B reused across 2 m-tiles ----
        float acc[2][4][4];
        #pragma unroll
        for (int mt = 0; mt < 2; mt++)
            #pragma unroll
            for (int jj = 0; jj < 4; jj++)
                #pragma unroll
                for (int c = 0; c < 4; c++) acc[mt][jj][c] = 0.f;

        #pragma unroll
        for (int ks = 0; ks < 8; ks++) {
            const uint32_t* ar0 = Au + (pb + gid) * APW + 8 * ks + tig;
            const uint32_t* ar1 = ar0 + 16 * APW;
            const uint32_t a00 = ar0[0], a02 = ar0[4];
            const uint32_t a01 = ar0[8 * APW], a03 = ar0[8 * APW + 4];
            const uint32_t a10 = ar1[0], a12 = ar1[4];
            const uint32_t a11 = ar1[8 * APW], a13 = ar1[8 * APW + 4];
            const uint4 bf0 = Bp[(ks * 4 + 2 * nhalf) * 32 + lane];
            const uint4 bf1 = Bp[(ks * 4 + 2 * nhalf + 1) * 32 + lane];
            mma_f16(acc[0][0], a00, a01, a02, a03, bf0.x, bf0.y);
            mma_f16(acc[0][1], a00, a01, a02, a03, bf0.z, bf0.w);
            mma_f16(acc[0][2], a00, a01, a02, a03, bf1.x, bf1.y);
            mma_f16(acc[0][3], a00, a01, a02, a03, bf1.z, bf1.w);
            mma_f16(acc[1][0], a10, a11, a12, a13, bf0.x, bf0.y);
            mma_f16(acc[1][1], a10, a11, a12, a13, bf0.z, bf0.w);
            mma_f16(acc[1][2], a10, a11, a12, a13, bf1.x, bf1.y);
            mma_f16(acc[1][3], a10, a11, a12, a13, bf1.z, bf1.w);
        }

        // ---- Epilogue: bias + ELU + dot(W2) over this warp's 32 n's ----
        #pragma unroll
        for (int mt = 0; mt < 2; mt++) {
            float p0 = 0.f, p1 = 0.f;
            #pragma unroll
            for (int jj = 0; jj < 4; jj++) {
                const int n = (nhalf * 4 + jj) * 8 + 2 * tig;
                const float bb0 = b1s[n], bb1 = b1s[n + 1];
                const float ww0 = w2s[n], ww1 = w2s[n + 1];
                float x;
                x = acc[mt][jj][0] + bb0; p0 = fmaf(x > 0.f ? x : (__expf(x) - 1.f), ww0, p0);
                x = acc[mt][jj][1] + bb1; p0 = fmaf(x > 0.f ? x : (__expf(x) - 1.f), ww1, p0);
                x = acc[mt][jj][2] + bb0; p1 = fmaf(x > 0.f ? x : (__expf(x) - 1.f), ww0, p1);
                x = acc[mt][jj][3] + bb1; p1 = fmaf(x > 0.f ? x : (__expf(x) - 1.f), ww1, p1);
            }
            p0 += __shfl_xor_sync(0xffffffffu, p0, 1);
            p0 += __shfl_xor_sync(0xffffffffu, p0, 2);
            p1 += __shfl_xor_sync(0xffffffffu, p1, 1);
            p1 += __shfl_xor_sync(0xffffffffu, p1, 2);
            if (tig == 0) {
                red[warp * 32 + mt * 16 + gid]     = p0;
                red[warp * 32 + mt * 16 + gid + 8] = p1;
            }
        }
        asm volatile("bar.sync %0, %1;" :: "r"(barid), "r"(64) : "memory");

        // ---- Finalize: each warp of the pair outputs 16 of the 32 edges ----
        if (lane < 16) {
            const int el = nhalf * 16 + lane;
            const float s = red[(pair * 2) * 32 + el] + red[(pair * 2 + 1) * 32 + el] + b2v;
            const int e = e0 + pb + el;
            if (e < EE) out[e] = 1.0f / (1.0f + __expf(-s));
        }
        // next gather's As writes are ordered by the post-gather bar.sync
    }
}

extern "C" void kernel_launch(void* const* d_in, const int* in_sizes, int n_in,
                              void* d_out, int out_size) {
    const float* z_in   = (const float*)d_in[0];
    const float* z_out  = (const float*)d_in[1];
    const float* z_self = (const float*)d_in[2];
    const int*   eidx   = (const int*)d_in[3];
    const float* W1     = (const float*)d_in[4];
    const float* b1     = (const float*)d_in[5];
    const float* W2     = (const float*)d_in[6];
    const float* b2     = (const float*)d_in[7];
    float*       outp   = (float*)d_out;

    prep_kernel<<<NN * CC / 8 / 256, 256>>>(z_in, z_out, z_self);

    const int smem_bytes = SMEM_FLOATS * (int)sizeof(float);   // 52736
    cudaFuncSetAttribute(gemm_kernel,
                         cudaFuncAttributeMaxDynamicSharedMemorySize, smem_bytes);
    gemm_kernel<<<MAIN_GRID, MAIN_THREADS, smem_bytes>>>(eidx, W1, b1, W2, b2, outp);
}